// round 1
// baseline (speedup 1.0000x reference)
#include <cuda_runtime.h>
#include <cuda_bf16.h>
#include <cstdint>

#define LL 16384
#define HH 1024
#define PP 512
#define NCHUNK 128
#define CHUNK 128

// ---------------- scratch (device globals; no runtime allocation) ----------------
__device__ float2 g_Lam[PP];                     // Lambda_bar
__device__ float2 g_F[PP];                       // (Lambda_bar-1)/Lambda
__device__ __nv_bfloat16 g_U[(size_t)LL * HH];        // u in bf16
__device__ __nv_bfloat16 g_Bcat[(size_t)(2 * PP) * HH]; // rows 0..511 = Bbar_re, 512..1023 = Bbar_im
__device__ __nv_bfloat16 g_Ccat[(size_t)HH * (2 * PP)]; // row h: [0..511]=C_re, [512..1023]=C_im
__device__ __nv_bfloat16 g_Bu[(size_t)LL * (2 * PP)];   // [l*1024+p]=re, +512=im (bf16-rounded)
__device__ __nv_bfloat16 g_X[(size_t)LL * (2 * PP)];    // scan states, bf16
__device__ float2 g_End[NCHUNK * PP];
__device__ float2 g_Carry[NCHUNK * PP];

// ---------------- helpers ----------------
__device__ __forceinline__ void cp_async16(void* smem_dst, const void* gmem_src) {
    unsigned dst = (unsigned)__cvta_generic_to_shared(smem_dst);
    asm volatile("cp.async.cg.shared.global [%0], [%1], 16;\n" :: "r"(dst), "l"(gmem_src));
}
__device__ __forceinline__ void cp_commit() { asm volatile("cp.async.commit_group;\n"); }
__device__ __forceinline__ void cp_wait0()  { asm volatile("cp.async.wait_group 0;\n"); }

__device__ __forceinline__ void mma16816(float* d, const unsigned* a, const unsigned* b) {
    asm volatile(
        "mma.sync.aligned.m16n8k16.row.col.f32.bf16.bf16.f32 "
        "{%0,%1,%2,%3}, {%4,%5,%6,%7}, {%8,%9}, {%0,%1,%2,%3};\n"
        : "+f"(d[0]), "+f"(d[1]), "+f"(d[2]), "+f"(d[3])
        : "r"(a[0]), "r"(a[1]), "r"(a[2]), "r"(a[3]), "r"(b[0]), "r"(b[1]));
}

// ---------------- prep kernels ----------------
__global__ void prep_lambda_kernel(const float* __restrict__ Lre,
                                   const float* __restrict__ Lim,
                                   const float* __restrict__ logstep) {
    int p = threadIdx.x;
    if (p >= PP) return;
    // compute in double: avoids fast-math sin/cos breakage for args up to ~160
    double step = exp((double)logstep[p]);
    double lr = (double)Lre[p], li = (double)Lim[p];
    double a = lr * step, b = li * step;
    double er = exp(a);
    double s = sin(b), c = cos(b);
    float Lbr = (float)(er * c), Lbi = (float)(er * s);
    g_Lam[p] = make_float2(Lbr, Lbi);
    double dr = (double)Lbr - 1.0, di = (double)Lbi;
    double den = lr * lr + li * li;
    float fr = (float)((dr * lr + di * li) / den);
    float fi = (float)((di * lr - dr * li) / den);
    g_F[p] = make_float2(fr, fi);
}

__global__ void prep_B_kernel(const float* __restrict__ B_re, const float* __restrict__ B_im) {
    int i = blockIdx.x * blockDim.x + threadIdx.x;   // over P*H
    if (i >= PP * HH) return;
    int p = i >> 10, h = i & 1023;
    float2 f = g_F[p];
    float br = B_re[i], bi = B_im[i];
    float re = f.x * br - f.y * bi;
    float im = f.x * bi + f.y * br;
    g_Bcat[(size_t)p * HH + h]        = __float2bfloat16_rn(re);
    g_Bcat[(size_t)(PP + p) * HH + h] = __float2bfloat16_rn(im);
}

__global__ void prep_C_kernel(const float* __restrict__ C_re, const float* __restrict__ C_im) {
    int i = blockIdx.x * blockDim.x + threadIdx.x;   // over H*P
    if (i >= HH * PP) return;
    int h = i >> 9, p = i & 511;
    g_Ccat[(size_t)h * 1024 + p]       = __float2bfloat16_rn(C_re[i]);
    g_Ccat[(size_t)h * 1024 + 512 + p] = __float2bfloat16_rn(C_im[i]);
}

__global__ void prep_U_kernel(const float* __restrict__ u) {
    int i = blockIdx.x * blockDim.x + threadIdx.x;   // over L*H/4
    if (i >= (LL * HH) / 4) return;
    float4 v = ((const float4*)u)[i];
    __nv_bfloat162 lo, hi;
    lo.x = __float2bfloat16_rn(v.x); lo.y = __float2bfloat16_rn(v.y);
    hi.x = __float2bfloat16_rn(v.z); hi.y = __float2bfloat16_rn(v.w);
    ((__nv_bfloat162*)g_U)[2 * (size_t)i]     = lo;
    ((__nv_bfloat162*)g_U)[2 * (size_t)i + 1] = hi;
}

// ---------------- GEMM1: Bu = u_bf @ Bcat^T  (L x 1024, K=H) ----------------
// BM=128 BN=128 BK=32, 8 warps (2x4), warp tile 64x32
__global__ __launch_bounds__(256) void gemm_bu_kernel() {
    __shared__ __align__(16) __nv_bfloat16 As[2][128 * 40];
    __shared__ __align__(16) __nv_bfloat16 Bs[2][128 * 40];
    const int tid = threadIdx.x;
    const int warp = tid >> 5, lane = tid & 31;
    const int wm = warp >> 2, wn = warp & 3;
    const int g = lane >> 2, t = lane & 3;
    const int bm = blockIdx.x * 128;
    const int bn = blockIdx.y * 128;

    float acc[4][4][4];
    #pragma unroll
    for (int i = 0; i < 4; i++)
        #pragma unroll
        for (int j = 0; j < 4; j++)
            #pragma unroll
            for (int k = 0; k < 4; k++) acc[i][j][k] = 0.f;

    const int arow = tid >> 2, ach = tid & 3;

    #pragma unroll
    for (int it = 0; it < 2; ++it) {
        int row = arow + it * 64;
        cp_async16(&As[0][row * 40 + ach * 8], g_U    + (size_t)(bm + row) * HH + ach * 8);
        cp_async16(&Bs[0][row * 40 + ach * 8], g_Bcat + (size_t)(bn + row) * HH + ach * 8);
    }
    cp_commit();

    const int NK = HH / 32;
    for (int ks = 0; ks < NK; ++ks) {
        cp_wait0();
        __syncthreads();
        if (ks + 1 < NK) {
            int k0 = (ks + 1) * 32;
            int nb = (ks + 1) & 1;
            #pragma unroll
            for (int it = 0; it < 2; ++it) {
                int row = arow + it * 64;
                cp_async16(&As[nb][row * 40 + ach * 8], g_U    + (size_t)(bm + row) * HH + k0 + ach * 8);
                cp_async16(&Bs[nb][row * 40 + ach * 8], g_Bcat + (size_t)(bn + row) * HH + k0 + ach * 8);
            }
            cp_commit();
        }
        int buf = ks & 1;
        #pragma unroll
        for (int kk = 0; kk < 32; kk += 16) {
            unsigned af[4][4], bfr[4][2];
            #pragma unroll
            for (int mt = 0; mt < 4; mt++) {
                const __nv_bfloat16* p0 = &As[buf][(wm * 64 + mt * 16 + g) * 40 + kk + 2 * t];
                af[mt][0] = *(const unsigned*)p0;
                af[mt][1] = *(const unsigned*)(p0 + 8 * 40);
                af[mt][2] = *(const unsigned*)(p0 + 8);
                af[mt][3] = *(const unsigned*)(p0 + 8 * 40 + 8);
            }
            #pragma unroll
            for (int nt = 0; nt < 4; nt++) {
                const __nv_bfloat16* p0 = &Bs[buf][(wn * 32 + nt * 8 + g) * 40 + kk + 2 * t];
                bfr[nt][0] = *(const unsigned*)p0;
                bfr[nt][1] = *(const unsigned*)(p0 + 8);
            }
            #pragma unroll
            for (int mt = 0; mt < 4; mt++)
                #pragma unroll
                for (int nt = 0; nt < 4; nt++)
                    mma16816(acc[mt][nt], af[mt], bfr[nt]);
        }
    }

    #pragma unroll
    for (int mt = 0; mt < 4; mt++) {
        #pragma unroll
        for (int nt = 0; nt < 4; nt++) {
            int r0 = bm + wm * 64 + mt * 16 + g;
            int c0 = bn + wn * 32 + nt * 8 + 2 * t;
            __nv_bfloat162 v;
            v.x = __float2bfloat16_rn(acc[mt][nt][0]);
            v.y = __float2bfloat16_rn(acc[mt][nt][1]);
            *(__nv_bfloat162*)&g_Bu[(size_t)r0 * 1024 + c0] = v;
            v.x = __float2bfloat16_rn(acc[mt][nt][2]);
            v.y = __float2bfloat16_rn(acc[mt][nt][3]);
            *(__nv_bfloat162*)&g_Bu[(size_t)(r0 + 8) * 1024 + c0] = v;
        }
    }
}

// ---------------- scan: x_t = Lam*x_{t-1} + Bu_t (complex, per channel) ----------------
__global__ void scan_pass1() {
    int p = threadIdx.x;
    int c = blockIdx.x;
    float2 Lam = g_Lam[p];
    float xr = 0.f, xi = 0.f;
    const __nv_bfloat16* bu = g_Bu + (size_t)c * CHUNK * 1024;
    for (int tt = 0; tt < CHUNK; tt++) {
        float br = __bfloat162float(bu[tt * 1024 + p]);
        float bi = __bfloat162float(bu[tt * 1024 + 512 + p]);
        float nr = fmaf(Lam.x, xr, fmaf(-Lam.y, xi, br));
        float ni = fmaf(Lam.x, xi, fmaf(Lam.y, xr, bi));
        xr = nr; xi = ni;
    }
    g_End[c * PP + p] = make_float2(xr, xi);
}

__global__ void scan_pass2() {
    int p = threadIdx.x;
    float2 Lam = g_Lam[p];
    float wr = Lam.x, wi = Lam.y;          // Lam^128 by 7 squarings
    #pragma unroll
    for (int s = 0; s < 7; s++) {
        float nr = wr * wr - wi * wi;
        float ni = 2.f * wr * wi;
        wr = nr; wi = ni;
    }
    float cr = 0.f, ci = 0.f;
    for (int c = 0; c < NCHUNK; c++) {
        g_Carry[c * PP + p] = make_float2(cr, ci);   // exclusive carry
        float2 e = g_End[c * PP + p];
        float nr = fmaf(wr, cr, fmaf(-wi, ci, e.x));
        float ni = fmaf(wr, ci, fmaf(wi, cr, e.y));
        cr = nr; ci = ni;
    }
}

__global__ void scan_pass3() {
    int p = threadIdx.x;
    int c = blockIdx.x;
    float2 Lam = g_Lam[p];
    float2 cin = g_Carry[c * PP + p];
    float xr = cin.x, xi = cin.y;
    const __nv_bfloat16* bu = g_Bu + (size_t)c * CHUNK * 1024;
    __nv_bfloat16* xo = g_X + (size_t)c * CHUNK * 1024;
    for (int tt = 0; tt < CHUNK; tt++) {
        float br = __bfloat162float(bu[tt * 1024 + p]);
        float bi = __bfloat162float(bu[tt * 1024 + 512 + p]);
        float nr = fmaf(Lam.x, xr, fmaf(-Lam.y, xi, br));
        float ni = fmaf(Lam.x, xi, fmaf(Lam.y, xr, bi));
        xr = nr; xi = ni;
        xo[tt * 1024 + p]       = __float2bfloat16_rn(xr);
        xo[tt * 1024 + 512 + p] = __float2bfloat16_rn(xi);
    }
}

// ---------------- GEMM2: rr = x_re @ C_re^T, ii = x_im @ C_im^T (dual accum) ----------------
// BM=128 BN=64 BK=32, 8 warps (4x2), warp tile 32x32
__global__ __launch_bounds__(256) void gemm_y_kernel(const float* __restrict__ u,
                                                     const float* __restrict__ Dv,
                                                     float* __restrict__ out) {
    extern __shared__ __align__(16) __nv_bfloat16 sm[];
    __nv_bfloat16* Are = sm;                     // 2 * 128*40
    __nv_bfloat16* Aim = Are + 2 * 128 * 40;     // 2 * 128*40
    __nv_bfloat16* Bre = Aim + 2 * 128 * 40;     // 2 * 64*40
    __nv_bfloat16* Bim = Bre + 2 * 64 * 40;      // 2 * 64*40

    const int tid = threadIdx.x;
    const int warp = tid >> 5, lane = tid & 31;
    const int wm = warp >> 1, wn = warp & 1;
    const int g = lane >> 2, t = lane & 3;
    const int bm = blockIdx.x * 128;
    const int bn = blockIdx.y * 64;

    float accR[2][4][4], accI[2][4][4];
    #pragma unroll
    for (int i = 0; i < 2; i++)
        #pragma unroll
        for (int j = 0; j < 4; j++)
            #pragma unroll
            for (int k = 0; k < 4; k++) { accR[i][j][k] = 0.f; accI[i][j][k] = 0.f; }

    const int arow = tid >> 2, ach = tid & 3;

    #pragma unroll
    for (int it = 0; it < 2; ++it) {
        int row = arow + it * 64;
        cp_async16(&Are[row * 40 + ach * 8], g_X + (size_t)(bm + row) * 1024 + ach * 8);
        cp_async16(&Aim[row * 40 + ach * 8], g_X + (size_t)(bm + row) * 1024 + 512 + ach * 8);
    }
    {
        int row = tid >> 2, ch = tid & 3;   // 64 rows x 4 chunks
        cp_async16(&Bre[row * 40 + ch * 8], g_Ccat + (size_t)(bn + row) * 1024 + ch * 8);
        cp_async16(&Bim[row * 40 + ch * 8], g_Ccat + (size_t)(bn + row) * 1024 + 512 + ch * 8);
    }
    cp_commit();

    const int NK = 512 / 32;  // 16
    for (int ks = 0; ks < NK; ++ks) {
        cp_wait0();
        __syncthreads();
        if (ks + 1 < NK) {
            int k0 = (ks + 1) * 32;
            int nb = (ks + 1) & 1;
            #pragma unroll
            for (int it = 0; it < 2; ++it) {
                int row = arow + it * 64;
                cp_async16(&Are[nb * 5120 + row * 40 + ach * 8], g_X + (size_t)(bm + row) * 1024 + k0 + ach * 8);
                cp_async16(&Aim[nb * 5120 + row * 40 + ach * 8], g_X + (size_t)(bm + row) * 1024 + 512 + k0 + ach * 8);
            }
            {
                int row = tid >> 2, ch = tid & 3;
                cp_async16(&Bre[nb * 2560 + row * 40 + ch * 8], g_Ccat + (size_t)(bn + row) * 1024 + k0 + ch * 8);
                cp_async16(&Bim[nb * 2560 + row * 40 + ch * 8], g_Ccat + (size_t)(bn + row) * 1024 + 512 + k0 + ch * 8);
            }
            cp_commit();
        }
        int buf = ks & 1;
        #pragma unroll
        for (int kk = 0; kk < 32; kk += 16) {
            unsigned aR[2][4], aI[2][4], bR[4][2], bI[4][2];
            #pragma unroll
            for (int mt = 0; mt < 2; mt++) {
                int r = (wm * 32 + mt * 16 + g) * 40 + kk + 2 * t;
                const __nv_bfloat16* pr = &Are[buf * 5120 + r];
                const __nv_bfloat16* pi = &Aim[buf * 5120 + r];
                aR[mt][0] = *(const unsigned*)pr;
                aR[mt][1] = *(const unsigned*)(pr + 8 * 40);
                aR[mt][2] = *(const unsigned*)(pr + 8);
                aR[mt][3] = *(const unsigned*)(pr + 8 * 40 + 8);
                aI[mt][0] = *(const unsigned*)pi;
                aI[mt][1] = *(const unsigned*)(pi + 8 * 40);
                aI[mt][2] = *(const unsigned*)(pi + 8);
                aI[mt][3] = *(const unsigned*)(pi + 8 * 40 + 8);
            }
            #pragma unroll
            for (int nt = 0; nt < 4; nt++) {
                int r = (wn * 32 + nt * 8 + g) * 40 + kk + 2 * t;
                const __nv_bfloat16* pr = &Bre[buf * 2560 + r];
                const __nv_bfloat16* pi = &Bim[buf * 2560 + r];
                bR[nt][0] = *(const unsigned*)pr;
                bR[nt][1] = *(const unsigned*)(pr + 8);
                bI[nt][0] = *(const unsigned*)pi;
                bI[nt][1] = *(const unsigned*)(pi + 8);
            }
            #pragma unroll
            for (int mt = 0; mt < 2; mt++)
                #pragma unroll
                for (int nt = 0; nt < 4; nt++) {
                    mma16816(accR[mt][nt], aR[mt], bR[nt]);
                    mma16816(accI[mt][nt], aI[mt], bI[nt]);
                }
        }
    }

    // epilogue: out = 2*bf16(bf16(rr) - bf16(ii)) + D*u
    #pragma unroll
    for (int mt = 0; mt < 2; mt++) {
        #pragma unroll
        for (int nt = 0; nt < 4; nt++) {
            #pragma unroll
            for (int j = 0; j < 4; j++) {
                int row = bm + wm * 32 + mt * 16 + g + ((j >= 2) ? 8 : 0);
                int col = bn + wn * 32 + nt * 8 + 2 * t + (j & 1);
                float rr = accR[mt][nt][j], ii = accI[mt][nt][j];
                __nv_bfloat16 db = __hsub(__float2bfloat16_rn(rr), __float2bfloat16_rn(ii));
                float uu = u[(size_t)row * 1024 + col];
                out[(size_t)row * 1024 + col] = fmaf(2.f, __bfloat162float(db), Dv[col] * uu);
            }
        }
    }
}

// ---------------- launch ----------------
extern "C" void kernel_launch(void* const* d_in, const int* in_sizes, int n_in,
                              void* d_out, int out_size) {
    const float* u       = (const float*)d_in[0];
    const float* LamRe   = (const float*)d_in[1];
    const float* LamIm   = (const float*)d_in[2];
    const float* B_re    = (const float*)d_in[3];
    const float* B_im    = (const float*)d_in[4];
    const float* C_re    = (const float*)d_in[5];
    const float* C_im    = (const float*)d_in[6];
    const float* Dv      = (const float*)d_in[7];
    const float* logstep = (const float*)d_in[8];
    float* out = (float*)d_out;

    prep_lambda_kernel<<<1, 512>>>(LamRe, LamIm, logstep);
    prep_B_kernel<<<(PP * HH) / 256, 256>>>(B_re, B_im);
    prep_C_kernel<<<(HH * PP) / 256, 256>>>(C_re, C_im);
    prep_U_kernel<<<(LL * HH) / 4 / 256, 256>>>(u);

    gemm_bu_kernel<<<dim3(LL / 128, 1024 / 128), 256>>>();

    scan_pass1<<<NCHUNK, PP>>>();
    scan_pass2<<<1, PP>>>();
    scan_pass3<<<NCHUNK, PP>>>();

    const int smem2 = (2 * 128 * 40 + 2 * 128 * 40 + 2 * 64 * 40 + 2 * 64 * 40) * (int)sizeof(__nv_bfloat16);
    cudaFuncSetAttribute(gemm_y_kernel, cudaFuncAttributeMaxDynamicSharedMemorySize, smem2);
    gemm_y_kernel<<<dim3(LL / 128, HH / 64), 256, smem2>>>(u, Dv, out);
}

// round 6
// speedup vs baseline: 1.1386x; 1.1386x over previous
#include <cuda_runtime.h>
#include <cuda_bf16.h>
#include <cstdint>

#define LL 16384
#define HH 1024
#define PP 512
#define NCHUNK 128
#define CHUNK 128

// ---- HMMA GEMM config ----
#define BSTRIDE 72                    // bf16 elems per smem row (64 + 8 pad); 144B
#define A_BYTES (128 * BSTRIDE * 2)   // 18432
#define STAGE_B (2 * A_BYTES)         // 36864
#define NSTAGE 4
#define GSMEM (NSTAGE * STAGE_B)      // 147456
#define GNK 16                        // K iters of 64 (both GEMMs span 1024 cols)

// ---------------- scratch (device globals) ----------------
__device__ float2 g_Lam[PP];
__device__ float2 g_F[PP];
__device__ __nv_bfloat16 g_U[(size_t)LL * HH];
__device__ __nv_bfloat16 g_Bcat[(size_t)(2 * PP) * HH];   // rows 0..511 Bbar_re, 512..1023 Bbar_im
__device__ __nv_bfloat16 g_Ccat[(size_t)HH * (2 * PP)];   // row h: [0..511]=C_re, [512..1023]=C_im
__device__ __nv_bfloat16 g_Bu[(size_t)LL * (2 * PP)];
__device__ __nv_bfloat16 g_X[(size_t)LL * (2 * PP)];      // row l: [0..511]=x_re, [512..1023]=x_im
__device__ float2 g_End[NCHUNK * PP];
__device__ float2 g_Carry[NCHUNK * PP];

// ---------------- helpers ----------------
__device__ __forceinline__ uint32_t smem_u32(const void* p) {
    uint32_t a;
    asm("{ .reg .u64 t; cvta.to.shared.u64 t, %1; cvt.u32.u64 %0, t; }" : "=r"(a) : "l"(p));
    return a;
}
__device__ __forceinline__ void cp_async16(uint32_t smem_dst, const void* gmem_src) {
    asm volatile("cp.async.cg.shared.global [%0], [%1], 16;\n" :: "r"(smem_dst), "l"(gmem_src));
}
__device__ __forceinline__ void cp_commit() { asm volatile("cp.async.commit_group;\n"); }

__device__ __forceinline__ void ldsm_x4(unsigned* r, uint32_t addr) {
    asm volatile("ldmatrix.sync.aligned.m8n8.x4.shared.b16 {%0,%1,%2,%3}, [%4];"
                 : "=r"(r[0]), "=r"(r[1]), "=r"(r[2]), "=r"(r[3]) : "r"(addr));
}
__device__ __forceinline__ void mma16816(float* d, const unsigned* a, const unsigned* b) {
    asm volatile(
        "mma.sync.aligned.m16n8k16.row.col.f32.bf16.bf16.f32 "
        "{%0,%1,%2,%3}, {%4,%5,%6,%7}, {%8,%9}, {%0,%1,%2,%3};\n"
        : "+f"(d[0]), "+f"(d[1]), "+f"(d[2]), "+f"(d[3])
        : "r"(a[0]), "r"(a[1]), "r"(a[2]), "r"(a[3]), "r"(b[0]), "r"(b[1]));
}

// ---------------- prep kernels ----------------
__global__ void prep_lambda_kernel(const float* __restrict__ Lre,
                                   const float* __restrict__ Lim,
                                   const float* __restrict__ logstep) {
    int p = threadIdx.x;
    if (p >= PP) return;
    double step = exp((double)logstep[p]);
    double lr = (double)Lre[p], li = (double)Lim[p];
    double a = lr * step, b = li * step;
    double er = exp(a);
    double s = sin(b), c = cos(b);
    float Lbr = (float)(er * c), Lbi = (float)(er * s);
    g_Lam[p] = make_float2(Lbr, Lbi);
    double dr = (double)Lbr - 1.0, di = (double)Lbi;
    double den = lr * lr + li * li;
    float fr = (float)((dr * lr + di * li) / den);
    float fi = (float)((di * lr - dr * li) / den);
    g_F[p] = make_float2(fr, fi);
}

__global__ void prep_B_kernel(const float* __restrict__ B_re, const float* __restrict__ B_im) {
    int i = blockIdx.x * blockDim.x + threadIdx.x;
    if (i >= PP * HH) return;
    int p = i >> 10, h = i & 1023;
    float2 f = g_F[p];
    float br = B_re[i], bi = B_im[i];
    float re = f.x * br - f.y * bi;
    float im = f.x * bi + f.y * br;
    g_Bcat[(size_t)p * HH + h]        = __float2bfloat16_rn(re);
    g_Bcat[(size_t)(PP + p) * HH + h] = __float2bfloat16_rn(im);
}

__global__ void prep_C_kernel(const float* __restrict__ C_re, const float* __restrict__ C_im) {
    int i = blockIdx.x * blockDim.x + threadIdx.x;
    if (i >= HH * PP) return;
    int h = i >> 9, p = i & 511;
    g_Ccat[(size_t)h * 1024 + p]       = __float2bfloat16_rn(C_re[i]);
    g_Ccat[(size_t)h * 1024 + 512 + p] = __float2bfloat16_rn(C_im[i]);
}

__global__ void prep_U_kernel(const float* __restrict__ u) {
    int i = blockIdx.x * blockDim.x + threadIdx.x;
    if (i >= (LL * HH) / 4) return;
    float4 v = ((const float4*)u)[i];
    __nv_bfloat162 lo, hi;
    lo.x = __float2bfloat16_rn(v.x); lo.y = __float2bfloat16_rn(v.y);
    hi.x = __float2bfloat16_rn(v.z); hi.y = __float2bfloat16_rn(v.w);
    ((__nv_bfloat162*)g_U)[2 * (size_t)i]     = lo;
    ((__nv_bfloat162*)g_U)[2 * (size_t)i + 1] = hi;
}

// ---------------- HMMA GEMM: BM=128 BN=128 BK=64, 256 thr, warp tile 64x32 ----------------
// MODE 0: Bu = u_bf @ Bcat^T  (K=1024), bf16 out
// MODE 1: phase0 (ks 0..7):  rr = x_re @ C_re^T  -> round to bf16, stash
//         phase1 (ks 8..15): ii = x_im @ C_im^T
//         out = 2*float(bf16(rr) - bf16(ii)) + D*u, fp32 out
template <int MODE>
__global__ __launch_bounds__(256, 1)
void gemm_hmma_kernel(const float* __restrict__ u, const float* __restrict__ Dv,
                      float* __restrict__ out) {
    extern __shared__ __align__(16) char smem[];
    const uint32_t smem_base = smem_u32(smem);
    const int tid = threadIdx.x;
    const int warp = tid >> 5, lane = tid & 31;
    const int wm = warp >> 2, wn = warp & 3;     // 2 x 4 warps
    const int g = lane >> 2, t = lane & 3;
    const int bm = blockIdx.x * 128;
    const int bn = blockIdx.y * 128;
    const __nv_bfloat16* Asrc = (MODE == 0) ? g_U : g_X;
    const __nv_bfloat16* Bsrc = (MODE == 0) ? g_Bcat : g_Ccat;

    float acc[4][4][4];
    #pragma unroll
    for (int i = 0; i < 4; i++)
        #pragma unroll
        for (int j = 0; j < 4; j++)
            #pragma unroll
            for (int k = 0; k < 4; k++) acc[i][j][k] = 0.f;
    uint32_t rrs[4][4][2];   // MODE1: stashed bf16(rr)

    // ldmatrix per-lane base offsets (bytes), stride 144B/row
    const int tI = lane >> 3, tr = lane & 7;
    const uint32_t a_off = (uint32_t)((wm * 64 + (tI & 1) * 8 + tr) * 144 + (tI >> 1) * 16);
    const uint32_t b_off = (uint32_t)((wn * 32 + (tI >> 1) * 8 + tr) * 144 + (tI & 1) * 16);

    // ---- stage loader: A 1024 chunks + B 1024 chunks of 16B, 8 per thread ----
    auto load_stage = [&](int s) {
        const uint32_t base = smem_base + (uint32_t)(s & 3) * STAGE_B;
        const int kc = s * 64;
        #pragma unroll
        for (int j = 0; j < 8; j++) {
            int idx = tid + j * 256;
            int mat = idx >> 10;            // 0 = A, 1 = B (constant per j)
            int loc = idx & 1023;
            int row = loc >> 3, ch = loc & 7;
            uint32_t dst = base + (uint32_t)mat * A_BYTES + (uint32_t)row * 144 + (uint32_t)ch * 16;
            const __nv_bfloat16* src = (mat ? Bsrc + (size_t)(bn + row) * 1024
                                            : Asrc + (size_t)(bm + row) * 1024) + kc + ch * 8;
            cp_async16(dst, src);
        }
        cp_commit();
    };

    load_stage(0); load_stage(1); load_stage(2);

    for (int ks = 0; ks < GNK; ks++) {
        {   // drain so stage ks is resident (tail-correct)
            int rem = GNK - 1 - ks;
            if (rem >= 2)      asm volatile("cp.async.wait_group 2;\n");
            else if (rem == 1) asm volatile("cp.async.wait_group 1;\n");
            else               asm volatile("cp.async.wait_group 0;\n");
        }
        __syncthreads();
        if (ks + 3 < GNK) load_stage(ks + 3);

        const uint32_t As = smem_base + (uint32_t)(ks & 3) * STAGE_B;
        const uint32_t Bs = As + A_BYTES;
        #pragma unroll
        for (int kk = 0; kk < 64; kk += 16) {
            unsigned af[4][4], bf[4][2];
            #pragma unroll
            for (int mt = 0; mt < 4; mt++)
                ldsm_x4(af[mt], As + a_off + (uint32_t)(mt * 16 * 144) + (uint32_t)(kk * 2));
            #pragma unroll
            for (int q = 0; q < 2; q++) {
                unsigned r[4];
                ldsm_x4(r, Bs + b_off + (uint32_t)(q * 16 * 144) + (uint32_t)(kk * 2));
                bf[2 * q][0] = r[0]; bf[2 * q][1] = r[1];
                bf[2 * q + 1][0] = r[2]; bf[2 * q + 1][1] = r[3];
            }
            #pragma unroll
            for (int mt = 0; mt < 4; mt++)
                #pragma unroll
                for (int nt = 0; nt < 4; nt++)
                    mma16816(acc[mt][nt], af[mt], bf[nt]);
        }

        if (MODE == 1 && ks == 7) {
            // stash bf16(rr), reset accumulators for ii phase
            #pragma unroll
            for (int mt = 0; mt < 4; mt++)
                #pragma unroll
                for (int nt = 0; nt < 4; nt++) {
                    __nv_bfloat162 v0, v1;
                    v0.x = __float2bfloat16_rn(acc[mt][nt][0]);
                    v0.y = __float2bfloat16_rn(acc[mt][nt][1]);
                    v1.x = __float2bfloat16_rn(acc[mt][nt][2]);
                    v1.y = __float2bfloat16_rn(acc[mt][nt][3]);
                    rrs[mt][nt][0] = *(uint32_t*)&v0;
                    rrs[mt][nt][1] = *(uint32_t*)&v1;
                    acc[mt][nt][0] = 0.f; acc[mt][nt][1] = 0.f;
                    acc[mt][nt][2] = 0.f; acc[mt][nt][3] = 0.f;
                }
        }
    }

    // ---- epilogue ----
    if (MODE == 0) {
        #pragma unroll
        for (int mt = 0; mt < 4; mt++) {
            #pragma unroll
            for (int nt = 0; nt < 4; nt++) {
                int r0 = bm + wm * 64 + mt * 16 + g;
                int c0 = bn + wn * 32 + nt * 8 + 2 * t;
                __nv_bfloat162 v;
                v.x = __float2bfloat16_rn(acc[mt][nt][0]);
                v.y = __float2bfloat16_rn(acc[mt][nt][1]);
                *(__nv_bfloat162*)&g_Bu[(size_t)r0 * 1024 + c0] = v;
                v.x = __float2bfloat16_rn(acc[mt][nt][2]);
                v.y = __float2bfloat16_rn(acc[mt][nt][3]);
                *(__nv_bfloat162*)&g_Bu[(size_t)(r0 + 8) * 1024 + c0] = v;
            }
        }
    } else {
        #pragma unroll
        for (int mt = 0; mt < 4; mt++) {
            #pragma unroll
            for (int nt = 0; nt < 4; nt++) {
                int r0 = bm + wm * 64 + mt * 16 + g;
                int c0 = bn + wn * 32 + nt * 8 + 2 * t;
                float d0 = __ldg(Dv + c0), d1 = __ldg(Dv + c0 + 1);
                #pragma unroll
                for (int half = 0; half < 2; half++) {
                    int row = r0 + half * 8;
                    __nv_bfloat162 rrv = *(__nv_bfloat162*)&rrs[mt][nt][half];
                    __nv_bfloat16 ii0 = __float2bfloat16_rn(acc[mt][nt][2 * half]);
                    __nv_bfloat16 ii1 = __float2bfloat16_rn(acc[mt][nt][2 * half + 1]);
                    float db0 = __bfloat162float(__hsub(rrv.x, ii0));
                    float db1 = __bfloat162float(__hsub(rrv.y, ii1));
                    const float2 uu = *(const float2*)(u + (size_t)row * 1024 + c0);
                    float2 ov;
                    ov.x = fmaf(2.f, db0, d0 * uu.x);
                    ov.y = fmaf(2.f, db1, d1 * uu.y);
                    *(float2*)(out + (size_t)row * 1024 + c0) = ov;
                }
            }
        }
    }
}

// ---------------- scan: x_t = Lam*x_{t-1} + Bu_t (complex, per channel) ----------------
__global__ void scan_pass1() {
    int p = threadIdx.x;
    int c = blockIdx.x;
    float2 Lam = g_Lam[p];
    float xr = 0.f, xi = 0.f;
    const __nv_bfloat16* bu = g_Bu + (size_t)c * CHUNK * 1024;
    for (int tt = 0; tt < CHUNK; tt++) {
        float br = __bfloat162float(bu[tt * 1024 + p]);
        float bi = __bfloat162float(bu[tt * 1024 + 512 + p]);
        float nr = fmaf(Lam.x, xr, fmaf(-Lam.y, xi, br));
        float ni = fmaf(Lam.x, xi, fmaf(Lam.y, xr, bi));
        xr = nr; xi = ni;
    }
    g_End[c * PP + p] = make_float2(xr, xi);
}

__global__ void scan_pass2() {
    int p = threadIdx.x;
    float2 Lam = g_Lam[p];
    float wr = Lam.x, wi = Lam.y;
    #pragma unroll
    for (int s = 0; s < 7; s++) {
        float nr = wr * wr - wi * wi;
        float ni = 2.f * wr * wi;
        wr = nr; wi = ni;
    }
    float cr = 0.f, ci = 0.f;
    for (int c = 0; c < NCHUNK; c++) {
        g_Carry[c * PP + p] = make_float2(cr, ci);
        float2 e = g_End[c * PP + p];
        float nr = fmaf(wr, cr, fmaf(-wi, ci, e.x));
        float ni = fmaf(wr, ci, fmaf(wi, cr, e.y));
        cr = nr; ci = ni;
    }
}

__global__ void scan_pass3() {
    int p = threadIdx.x;
    int c = blockIdx.x;
    float2 Lam = g_Lam[p];
    float2 cin = g_Carry[c * PP + p];
    float xr = cin.x, xi = cin.y;
    const __nv_bfloat16* bu = g_Bu + (size_t)c * CHUNK * 1024;
    __nv_bfloat16* xo = g_X + (size_t)c * CHUNK * 1024;
    for (int tt = 0; tt < CHUNK; tt++) {
        float br = __bfloat162float(bu[tt * 1024 + p]);
        float bi = __bfloat162float(bu[tt * 1024 + 512 + p]);
        float nr = fmaf(Lam.x, xr, fmaf(-Lam.y, xi, br));
        float ni = fmaf(Lam.x, xi, fmaf(Lam.y, xr, bi));
        xr = nr; xi = ni;
        xo[tt * 1024 + p]       = __float2bfloat16_rn(xr);
        xo[tt * 1024 + 512 + p] = __float2bfloat16_rn(xi);
    }
}

// ---------------- launch ----------------
extern "C" void kernel_launch(void* const* d_in, const int* in_sizes, int n_in,
                              void* d_out, int out_size) {
    const float* u       = (const float*)d_in[0];
    const float* LamRe   = (const float*)d_in[1];
    const float* LamIm   = (const float*)d_in[2];
    const float* B_re    = (const float*)d_in[3];
    const float* B_im    = (const float*)d_in[4];
    const float* C_re    = (const float*)d_in[5];
    const float* C_im    = (const float*)d_in[6];
    const float* Dv      = (const float*)d_in[7];
    const float* logstep = (const float*)d_in[8];
    float* out = (float*)d_out;

    prep_lambda_kernel<<<1, 512>>>(LamRe, LamIm, logstep);
    prep_B_kernel<<<(PP * HH) / 256, 256>>>(B_re, B_im);
    prep_C_kernel<<<(HH * PP) / 256, 256>>>(C_re, C_im);
    prep_U_kernel<<<(LL * HH) / 4 / 256, 256>>>(u);

    cudaFuncSetAttribute(gemm_hmma_kernel<0>, cudaFuncAttributeMaxDynamicSharedMemorySize, GSMEM);
    gemm_hmma_kernel<0><<<dim3(LL / 128, 8), 256, GSMEM>>>(nullptr, nullptr, nullptr);

    scan_pass1<<<NCHUNK, PP>>>();
    scan_pass2<<<1, PP>>>();
    scan_pass3<<<NCHUNK, PP>>>();

    cudaFuncSetAttribute(gemm_hmma_kernel<1>, cudaFuncAttributeMaxDynamicSharedMemorySize, GSMEM);
    gemm_hmma_kernel<1><<<dim3(LL / 128, 8), 256, GSMEM>>>(u, Dv, out);
}

// round 7
// speedup vs baseline: 1.1548x; 1.0143x over previous
#include <cuda_runtime.h>
#include <cuda_bf16.h>
#include <cstdint>

#define LL 16384
#define HH 1024
#define PP 512
#define NCHUNK 128
#define CHUNK 128

// ---- HMMA GEMM config ----
#define BSTRIDE 72                    // bf16 elems per smem row (64 + 8 pad); 144B
#define A_BYTES (128 * BSTRIDE * 2)   // 18432
#define STAGE_B (2 * A_BYTES)         // 36864
#define NSTAGE 4
#define GSMEM (NSTAGE * STAGE_B)      // 147456
#define GNK 16                        // K iters of 64 (both GEMMs span 1024 cols)

// ---------------- scratch (device globals) ----------------
__device__ float2 g_Lam[PP];
__device__ float2 g_F[PP];
__device__ __nv_bfloat16 g_U[(size_t)LL * HH];
__device__ __nv_bfloat16 g_Bcat[(size_t)(2 * PP) * HH];   // rows 0..511 Bbar_re, 512..1023 Bbar_im
__device__ __nv_bfloat16 g_Ccat[(size_t)HH * (2 * PP)];   // row h: [0..511]=C_re, [512..1023]=C_im
__device__ __nv_bfloat16 g_Bu[(size_t)LL * (2 * PP)];
__device__ __nv_bfloat16 g_X[(size_t)LL * (2 * PP)];      // row l: [0..511]=x_re, [512..1023]=x_im
__device__ float2 g_End[NCHUNK * PP];
__device__ float2 g_Carry[NCHUNK * PP];

// ---------------- helpers ----------------
__device__ __forceinline__ uint32_t smem_u32(const void* p) {
    uint32_t a;
    asm("{ .reg .u64 t; cvta.to.shared.u64 t, %1; cvt.u32.u64 %0, t; }" : "=r"(a) : "l"(p));
    return a;
}
__device__ __forceinline__ void cp_async16(uint32_t smem_dst, const void* gmem_src) {
    asm volatile("cp.async.cg.shared.global [%0], [%1], 16;\n" :: "r"(smem_dst), "l"(gmem_src));
}
__device__ __forceinline__ void cp_commit() { asm volatile("cp.async.commit_group;\n"); }

__device__ __forceinline__ void ldsm_x4(unsigned* r, uint32_t addr) {
    asm volatile("ldmatrix.sync.aligned.m8n8.x4.shared.b16 {%0,%1,%2,%3}, [%4];"
                 : "=r"(r[0]), "=r"(r[1]), "=r"(r[2]), "=r"(r[3]) : "r"(addr));
}
__device__ __forceinline__ void mma16816(float* d, const unsigned* a, const unsigned* b) {
    asm volatile(
        "mma.sync.aligned.m16n8k16.row.col.f32.bf16.bf16.f32 "
        "{%0,%1,%2,%3}, {%4,%5,%6,%7}, {%8,%9}, {%0,%1,%2,%3};\n"
        : "+f"(d[0]), "+f"(d[1]), "+f"(d[2]), "+f"(d[3])
        : "r"(a[0]), "r"(a[1]), "r"(a[2]), "r"(a[3]), "r"(b[0]), "r"(b[1]));
}

// ---------------- prep kernels ----------------
__global__ void prep_lambda_kernel(const float* __restrict__ Lre,
                                   const float* __restrict__ Lim,
                                   const float* __restrict__ logstep) {
    int p = threadIdx.x;
    if (p >= PP) return;
    double step = exp((double)logstep[p]);
    double lr = (double)Lre[p], li = (double)Lim[p];
    double a = lr * step, b = li * step;
    double er = exp(a);
    double s = sin(b), c = cos(b);
    float Lbr = (float)(er * c), Lbi = (float)(er * s);
    g_Lam[p] = make_float2(Lbr, Lbi);
    double dr = (double)Lbr - 1.0, di = (double)Lbi;
    double den = lr * lr + li * li;
    float fr = (float)((dr * lr + di * li) / den);
    float fi = (float)((di * lr - dr * li) / den);
    g_F[p] = make_float2(fr, fi);
}

__global__ void prep_B_kernel(const float* __restrict__ B_re, const float* __restrict__ B_im) {
    int i = blockIdx.x * blockDim.x + threadIdx.x;
    if (i >= PP * HH) return;
    int p = i >> 10, h = i & 1023;
    float2 f = g_F[p];
    float br = B_re[i], bi = B_im[i];
    float re = f.x * br - f.y * bi;
    float im = f.x * bi + f.y * br;
    g_Bcat[(size_t)p * HH + h]        = __float2bfloat16_rn(re);
    g_Bcat[(size_t)(PP + p) * HH + h] = __float2bfloat16_rn(im);
}

__global__ void prep_C_kernel(const float* __restrict__ C_re, const float* __restrict__ C_im) {
    int i = blockIdx.x * blockDim.x + threadIdx.x;
    if (i >= HH * PP) return;
    int h = i >> 9, p = i & 511;
    g_Ccat[(size_t)h * 1024 + p]       = __float2bfloat16_rn(C_re[i]);
    g_Ccat[(size_t)h * 1024 + 512 + p] = __float2bfloat16_rn(C_im[i]);
}

// 8 floats per thread -> one 16B bf16 store
__global__ void prep_U_kernel(const float* __restrict__ u) {
    int i = blockIdx.x * blockDim.x + threadIdx.x;
    if (i >= (LL * HH) / 8) return;
    float4 v0 = ((const float4*)u)[2 * (size_t)i];
    float4 v1 = ((const float4*)u)[2 * (size_t)i + 1];
    __nv_bfloat162 a, b, c, d;
    a.x = __float2bfloat16_rn(v0.x); a.y = __float2bfloat16_rn(v0.y);
    b.x = __float2bfloat16_rn(v0.z); b.y = __float2bfloat16_rn(v0.w);
    c.x = __float2bfloat16_rn(v1.x); c.y = __float2bfloat16_rn(v1.y);
    d.x = __float2bfloat16_rn(v1.z); d.y = __float2bfloat16_rn(v1.w);
    uint4 pk = make_uint4(*(uint32_t*)&a, *(uint32_t*)&b, *(uint32_t*)&c, *(uint32_t*)&d);
    ((uint4*)g_U)[i] = pk;
}

// ---------------- HMMA GEMM: BM=128 BN=128 BK=64, 512 thr (16 warps 4x4), warp tile 32x32 ----------------
// MODE 0: Bu = u_bf @ Bcat^T  (K=1024), bf16 out
// MODE 1: phase0 (ks 0..7):  rr = x_re @ C_re^T  -> round to bf16, stash
//         phase1 (ks 8..15): ii = x_im @ C_im^T
//         out = 2*float(bf16(rr) - bf16(ii)) + D*u, fp32 out
template <int MODE>
__global__ __launch_bounds__(512, 1)
void gemm_hmma_kernel(const float* __restrict__ u, const float* __restrict__ Dv,
                      float* __restrict__ out) {
    extern __shared__ __align__(16) char smem[];
    const uint32_t smem_base = smem_u32(smem);
    const int tid = threadIdx.x;
    const int warp = tid >> 5, lane = tid & 31;
    const int wm = warp >> 2, wn = warp & 3;     // 4 x 4 warps, warp tile 32x32
    const int g = lane >> 2, t = lane & 3;
    const int bm = blockIdx.x * 128;
    const int bn = blockIdx.y * 128;
    const __nv_bfloat16* Asrc = (MODE == 0) ? g_U : g_X;
    const __nv_bfloat16* Bsrc = (MODE == 0) ? g_Bcat : g_Ccat;

    float acc[2][4][4];
    #pragma unroll
    for (int i = 0; i < 2; i++)
        #pragma unroll
        for (int j = 0; j < 4; j++)
            #pragma unroll
            for (int k = 0; k < 4; k++) acc[i][j][k] = 0.f;
    uint32_t rrs[2][4][2];   // MODE1: stashed bf16(rr)

    // ldmatrix per-lane base offsets (bytes), stride 144B/row
    const int tI = lane >> 3, tr = lane & 7;
    const uint32_t a_off = (uint32_t)((wm * 32 + (tI & 1) * 8 + tr) * 144 + (tI >> 1) * 16);
    const uint32_t b_off = (uint32_t)((wn * 32 + (tI >> 1) * 8 + tr) * 144 + (tI & 1) * 16);

    // ---- stage loader: A 1024 chunks + B 1024 chunks of 16B, 4 per thread ----
    auto load_stage = [&](int s) {
        const uint32_t base = smem_base + (uint32_t)(s & 3) * STAGE_B;
        const int kc = s * 64;
        #pragma unroll
        for (int j = 0; j < 4; j++) {
            int idx = tid + j * 512;
            int mat = idx >> 10;            // 0 = A, 1 = B (constant per j)
            int loc = idx & 1023;
            int row = loc >> 3, ch = loc & 7;
            uint32_t dst = base + (uint32_t)mat * A_BYTES + (uint32_t)row * 144 + (uint32_t)ch * 16;
            const __nv_bfloat16* src = (mat ? Bsrc + (size_t)(bn + row) * 1024
                                            : Asrc + (size_t)(bm + row) * 1024) + kc + ch * 8;
            cp_async16(dst, src);
        }
        cp_commit();
    };

    load_stage(0); load_stage(1); load_stage(2);

    for (int ks = 0; ks < GNK; ks++) {
        {   // drain so stage ks is resident (tail-correct)
            int rem = GNK - 1 - ks;
            if (rem >= 2)      asm volatile("cp.async.wait_group 2;\n");
            else if (rem == 1) asm volatile("cp.async.wait_group 1;\n");
            else               asm volatile("cp.async.wait_group 0;\n");
        }
        __syncthreads();
        if (ks + 3 < GNK) load_stage(ks + 3);

        const uint32_t As = smem_base + (uint32_t)(ks & 3) * STAGE_B;
        const uint32_t Bs = As + A_BYTES;
        #pragma unroll
        for (int kk = 0; kk < 64; kk += 16) {
            unsigned af[2][4], bf[4][2];
            #pragma unroll
            for (int mt = 0; mt < 2; mt++)
                ldsm_x4(af[mt], As + a_off + (uint32_t)(mt * 16 * 144) + (uint32_t)(kk * 2));
            #pragma unroll
            for (int q = 0; q < 2; q++) {
                unsigned r[4];
                ldsm_x4(r, Bs + b_off + (uint32_t)(q * 16 * 144) + (uint32_t)(kk * 2));
                bf[2 * q][0] = r[0]; bf[2 * q][1] = r[1];
                bf[2 * q + 1][0] = r[2]; bf[2 * q + 1][1] = r[3];
            }
            #pragma unroll
            for (int mt = 0; mt < 2; mt++)
                #pragma unroll
                for (int nt = 0; nt < 4; nt++)
                    mma16816(acc[mt][nt], af[mt], bf[nt]);
        }

        if (MODE == 1 && ks == 7) {
            // stash bf16(rr), reset accumulators for ii phase
            #pragma unroll
            for (int mt = 0; mt < 2; mt++)
                #pragma unroll
                for (int nt = 0; nt < 4; nt++) {
                    __nv_bfloat162 v0, v1;
                    v0.x = __float2bfloat16_rn(acc[mt][nt][0]);
                    v0.y = __float2bfloat16_rn(acc[mt][nt][1]);
                    v1.x = __float2bfloat16_rn(acc[mt][nt][2]);
                    v1.y = __float2bfloat16_rn(acc[mt][nt][3]);
                    rrs[mt][nt][0] = *(uint32_t*)&v0;
                    rrs[mt][nt][1] = *(uint32_t*)&v1;
                    acc[mt][nt][0] = 0.f; acc[mt][nt][1] = 0.f;
                    acc[mt][nt][2] = 0.f; acc[mt][nt][3] = 0.f;
                }
        }
    }

    // ---- epilogue ----
    if (MODE == 0) {
        #pragma unroll
        for (int mt = 0; mt < 2; mt++) {
            #pragma unroll
            for (int nt = 0; nt < 4; nt++) {
                int r0 = bm + wm * 32 + mt * 16 + g;
                int c0 = bn + wn * 32 + nt * 8 + 2 * t;
                __nv_bfloat162 v;
                v.x = __float2bfloat16_rn(acc[mt][nt][0]);
                v.y = __float2bfloat16_rn(acc[mt][nt][1]);
                *(__nv_bfloat162*)&g_Bu[(size_t)r0 * 1024 + c0] = v;
                v.x = __float2bfloat16_rn(acc[mt][nt][2]);
                v.y = __float2bfloat16_rn(acc[mt][nt][3]);
                *(__nv_bfloat162*)&g_Bu[(size_t)(r0 + 8) * 1024 + c0] = v;
            }
        }
    } else {
        #pragma unroll
        for (int mt = 0; mt < 2; mt++) {
            #pragma unroll
            for (int nt = 0; nt < 4; nt++) {
                int r0 = bm + wm * 32 + mt * 16 + g;
                int c0 = bn + wn * 32 + nt * 8 + 2 * t;
                float d0 = __ldg(Dv + c0), d1 = __ldg(Dv + c0 + 1);
                #pragma unroll
                for (int half = 0; half < 2; half++) {
                    int row = r0 + half * 8;
                    __nv_bfloat162 rrv = *(__nv_bfloat162*)&rrs[mt][nt][half];
                    __nv_bfloat16 ii0 = __float2bfloat16_rn(acc[mt][nt][2 * half]);
                    __nv_bfloat16 ii1 = __float2bfloat16_rn(acc[mt][nt][2 * half + 1]);
                    float db0 = __bfloat162float(__hsub(rrv.x, ii0));
                    float db1 = __bfloat162float(__hsub(rrv.y, ii1));
                    const float2 uu = *(const float2*)(u + (size_t)row * 1024 + c0);
                    float2 ov;
                    ov.x = fmaf(2.f, db0, d0 * uu.x);
                    ov.y = fmaf(2.f, db1, d1 * uu.y);
                    *(float2*)(out + (size_t)row * 1024 + c0) = ov;
                }
            }
        }
    }
}

// ---------------- scan: x_t = Lam*x_{t-1} + Bu_t (complex, per channel) ----------------
__global__ void scan_pass1() {
    int p = threadIdx.x;
    int c = blockIdx.x;
    float2 Lam = g_Lam[p];
    float xr = 0.f, xi = 0.f;
    const __nv_bfloat16* bu = g_Bu + (size_t)c * CHUNK * 1024;
    for (int tt = 0; tt < CHUNK; tt++) {
        float br = __bfloat162float(bu[tt * 1024 + p]);
        float bi = __bfloat162float(bu[tt * 1024 + 512 + p]);
        float nr = fmaf(Lam.x, xr, fmaf(-Lam.y, xi, br));
        float ni = fmaf(Lam.x, xi, fmaf(Lam.y, xr, bi));
        xr = nr; xi = ni;
    }
    g_End[c * PP + p] = make_float2(xr, xi);
}

__global__ void scan_pass2() {
    int p = threadIdx.x;
    float2 Lam = g_Lam[p];
    float wr = Lam.x, wi = Lam.y;
    #pragma unroll
    for (int s = 0; s < 7; s++) {
        float nr = wr * wr - wi * wi;
        float ni = 2.f * wr * wi;
        wr = nr; wi = ni;
    }
    float cr = 0.f, ci = 0.f;
    for (int c = 0; c < NCHUNK; c++) {
        g_Carry[c * PP + p] = make_float2(cr, ci);
        float2 e = g_End[c * PP + p];
        float nr = fmaf(wr, cr, fmaf(-wi, ci, e.x));
        float ni = fmaf(wr, ci, fmaf(wi, cr, e.y));
        cr = nr; ci = ni;
    }
}

__global__ void scan_pass3() {
    int p = threadIdx.x;
    int c = blockIdx.x;
    float2 Lam = g_Lam[p];
    float2 cin = g_Carry[c * PP + p];
    float xr = cin.x, xi = cin.y;
    const __nv_bfloat16* bu = g_Bu + (size_t)c * CHUNK * 1024;
    __nv_bfloat16* xo = g_X + (size_t)c * CHUNK * 1024;
    for (int tt = 0; tt < CHUNK; tt++) {
        float br = __bfloat162float(bu[tt * 1024 + p]);
        float bi = __bfloat162float(bu[tt * 1024 + 512 + p]);
        float nr = fmaf(Lam.x, xr, fmaf(-Lam.y, xi, br));
        float ni = fmaf(Lam.x, xi, fmaf(Lam.y, xr, bi));
        xr = nr; xi = ni;
        xo[tt * 1024 + p]       = __float2bfloat16_rn(xr);
        xo[tt * 1024 + 512 + p] = __float2bfloat16_rn(xi);
    }
}

// ---------------- launch ----------------
extern "C" void kernel_launch(void* const* d_in, const int* in_sizes, int n_in,
                              void* d_out, int out_size) {
    const float* u       = (const float*)d_in[0];
    const float* LamRe   = (const float*)d_in[1];
    const float* LamIm   = (const float*)d_in[2];
    const float* B_re    = (const float*)d_in[3];
    const float* B_im    = (const float*)d_in[4];
    const float* C_re    = (const float*)d_in[5];
    const float* C_im    = (const float*)d_in[6];
    const float* Dv      = (const float*)d_in[7];
    const float* logstep = (const float*)d_in[8];
    float* out = (float*)d_out;

    prep_lambda_kernel<<<1, 512>>>(LamRe, LamIm, logstep);
    prep_B_kernel<<<(PP * HH) / 256, 256>>>(B_re, B_im);
    prep_C_kernel<<<(HH * PP) / 256, 256>>>(C_re, C_im);
    prep_U_kernel<<<(LL * HH) / 8 / 256, 256>>>(u);

    cudaFuncSetAttribute(gemm_hmma_kernel<0>, cudaFuncAttributeMaxDynamicSharedMemorySize, GSMEM);
    gemm_hmma_kernel<0><<<dim3(LL / 128, 8), 512, GSMEM>>>(nullptr, nullptr, nullptr);

    scan_pass1<<<NCHUNK, PP>>>();
    scan_pass2<<<1, PP>>>();
    scan_pass3<<<NCHUNK, PP>>>();

    cudaFuncSetAttribute(gemm_hmma_kernel<1>, cudaFuncAttributeMaxDynamicSharedMemorySize, GSMEM);
    gemm_hmma_kernel<1><<<dim3(LL / 128, 8), 512, GSMEM>>>(u, Dv, out);
}